// round 7
// baseline (speedup 1.0000x reference)
#include <cuda_runtime.h>
#include <cuda_fp16.h>
#include <cstdint>

// ---------------- problem constants ----------------
#define T_TOKENS 32768
#define E_DIM    512
#define GROUPS   4
#define DIM      128      // per-group dim (K)
#define KCODES   512      // codes per group (N)

#define MT       128      // tokens per CTA
#define THREADS  256

#define MARGIN   1e-2f    // covers int8 quantization error (Hoeffding ~1e-11/pair @5e-3) + fp16 store

// int8 scales: w_q = rint(w * 65024) (|w|<1/512 -> |w_q|<127), x_q = rint(x*16) clamp +-127
// cross = acc / (16*65024) = acc / 1040384 ; s = wsq - 2*cross = wsq - acc * 1.9223845e-6
#define S_CONST  (-1.9223845e-6f)

// ---- smem layout (bytes) ----
#define XQ_OFF    0            // 128 rows * 36 u32 = 18432
#define XQ_STRIDE 36
#define WQ_OFF    18432        // 512 rows * 36 u32 = 73728 -> 92160
#define WQ_STRIDE 36
#define S_OFF     92160        // u16: 128 * 514 = 131584 -> 223744
#define S_STRIDE16 514         // u16 stride (257 u32, conflict-free scan)
#define WSQ_OFF   223744       // 512*4 = 2048 -> 225792
#define THR_OFF   225792       // 128*4 -> 226304 (padded)
#define BK_OFF    226304       // 128*4 -> 226816 (padded)
#define PK_OFF    226816       // 128*8 = 1024 -> 227840
#define RED_OFF   227840       // 8*8 = 64 -> 227904
#define SMEM_TOTAL 227904

__device__ uint32_t g_wq[GROUPS * KCODES * (DIM / 4)];   // packed int8 codebook
__device__ float    g_wsq[GROUPS * KCODES];
__device__ double   g_loss_acc;

__global__ void vq_init_kernel() { g_loss_acc = 0.0; }

__global__ void vq_finalize_kernel(float* out, long long loss_index) {
    out[loss_index] = (float)(g_loss_acc * (1.25 / 4194304.0));
}

// Quantize W rows to packed int8 + exact wsq (sequential fp32 chain, ref order).
__global__ void vq_prep_kernel(const float* __restrict__ w0, const float* __restrict__ w1,
                               const float* __restrict__ w2, const float* __restrict__ w3)
{
    int r = blockIdx.x * blockDim.x + threadIdx.x;
    if (r >= GROUPS * KCODES) return;
    int g = r >> 9, k = r & (KCODES - 1);
    const float* W = (g == 0) ? w0 : (g == 1) ? w1 : (g == 2) ? w2 : w3;
    const float* row = W + (size_t)k * DIM;
    float s = 0.0f;
    #pragma unroll 4
    for (int c = 0; c < DIM / 4; ++c) {
        uint32_t packed = 0;
        #pragma unroll
        for (int q = 0; q < 4; ++q) {
            float x = row[c * 4 + q];
            s = fmaf(x, x, s);
            int qi = __float2int_rn(x * 65024.0f);
            qi = max(-127, min(127, qi));
            packed |= ((uint32_t)qi & 0xFFu) << (q * 8);
        }
        g_wq[(size_t)r * (DIM / 4) + c] = packed;
    }
    // s above accumulated in c-chunk order == sequential d order (c*4+q ascending)
    g_wsq[r] = s;
}

__global__ __launch_bounds__(THREADS, 1)
void vq_main_kernel(const float* __restrict__ latents,
                    const float* __restrict__ w0, const float* __restrict__ w1,
                    const float* __restrict__ w2, const float* __restrict__ w3,
                    float* __restrict__ out)
{
    extern __shared__ char sm[];
    uint32_t* xq      = (uint32_t*)(sm + XQ_OFF);
    uint32_t* wq      = (uint32_t*)(sm + WQ_OFF);
    uint16_t* s16     = (uint16_t*)(sm + S_OFF);
    float*    wsq_sm  = (float*)(sm + WSQ_OFF);
    float*    thr_sm  = (float*)(sm + THR_OFF);
    int*      bk_sm   = (int*)(sm + BK_OFF);
    uint64_t* pk_sm   = (uint64_t*)(sm + PK_OFF);
    double*   red     = (double*)(sm + RED_OFF);

    const int g  = blockIdx.y;
    const int t0 = blockIdx.x * MT;
    const float* __restrict__ W = (g == 0) ? w0 : (g == 1) ? w1 : (g == 2) ? w2 : w3;

    const int tid  = threadIdx.x;
    const int wid  = tid >> 5;
    const int lane = tid & 31;
    const int tx   = tid & 15;   // code lane
    const int ty   = tid >> 4;   // token lane

    // ---- load + quantize X tile (128 tokens x 128 dims -> packed int8) ----
    #pragma unroll
    for (int it = 0; it < 16; ++it) {
        int idx = tid + it * THREADS;          // 0..4095 u32-chunks
        int m   = idx >> 5;
        int c   = idx & 31;                    // u32 chunk (4 dims)
        float4 v = *(const float4*)(latents + (size_t)(t0 + m) * E_DIM + g * DIM + c * 4);
        int q0 = max(-127, min(127, __float2int_rn(v.x * 16.0f)));
        int q1 = max(-127, min(127, __float2int_rn(v.y * 16.0f)));
        int q2 = max(-127, min(127, __float2int_rn(v.z * 16.0f)));
        int q3 = max(-127, min(127, __float2int_rn(v.w * 16.0f)));
        uint32_t p = ((uint32_t)q0 & 0xFFu) | (((uint32_t)q1 & 0xFFu) << 8)
                   | (((uint32_t)q2 & 0xFFu) << 16) | (((uint32_t)q3 & 0xFFu) << 24);
        xq[m * XQ_STRIDE + c] = p;
    }
    // ---- load quantized W (all 512 codes) + wsq ----
    #pragma unroll
    for (int it = 0; it < 64; ++it) {
        int idx = tid + it * THREADS;          // 0..16383
        int r   = idx >> 5;
        int c   = idx & 31;
        wq[r * WQ_STRIDE + c] = g_wq[((size_t)(g * KCODES + r)) * (DIM / 4) + c];
    }
    for (int i = tid; i < KCODES; i += THREADS) wsq_sm[i] = g_wsq[g * KCODES + i];
    __syncthreads();

    // ---- phase A: dp4a filter GEMM, 4 passes of 128 codes ----
    float minf[8];
    #pragma unroll
    for (int i = 0; i < 8; ++i) minf[i] = 3.402823466e38f;

    for (int kt = 0; kt < 4; ++kt) {
        int acc[8][8];
        #pragma unroll
        for (int i = 0; i < 8; ++i)
            #pragma unroll
            for (int j = 0; j < 8; ++j) acc[i][j] = 0;

        #pragma unroll
        for (int ch = 0; ch < 8; ++ch) {       // uint4 chunks of the 32-u32 K dim
            uint4 xf[8];
            #pragma unroll
            for (int i = 0; i < 8; ++i)
                xf[i] = *(const uint4*)(xq + (ty + 16 * i) * XQ_STRIDE + ch * 4);
            #pragma unroll
            for (int j = 0; j < 8; ++j) {
                uint4 wf = *(const uint4*)(wq + (kt * 128 + tx + 16 * j) * WQ_STRIDE + ch * 4);
                #pragma unroll
                for (int i = 0; i < 8; ++i) {
                    acc[i][j] = __dp4a((int)xf[i].x, (int)wf.x, acc[i][j]);
                    acc[i][j] = __dp4a((int)xf[i].y, (int)wf.y, acc[i][j]);
                    acc[i][j] = __dp4a((int)xf[i].z, (int)wf.z, acc[i][j]);
                    acc[i][j] = __dp4a((int)xf[i].w, (int)wf.w, acc[i][j]);
                }
            }
        }
        // s = wsq - 2*cross_approx ; store fp16, track running min (of fp16-rounded value)
        #pragma unroll
        for (int j = 0; j < 8; ++j) {
            int k = kt * 128 + tx + 16 * j;
            float ws = wsq_sm[k];
            #pragma unroll
            for (int i = 0; i < 8; ++i) {
                float s = fmaf((float)acc[i][j], S_CONST, ws);
                __half hh = __float2half_rn(s);
                s16[(ty + 16 * i) * S_STRIDE16 + k] = *(uint16_t*)&hh;
                minf[i] = fminf(minf[i], __half2float(hh));
            }
        }
    }

    // per-token min across the 16 code-lanes -> threshold
    #pragma unroll
    for (int i = 0; i < 8; ++i) {
        float bd = minf[i];
        #pragma unroll
        for (int off = 1; off < 16; off <<= 1)
            bd = fminf(bd, __shfl_xor_sync(0xffffffffu, bd, off));
        if (tx == 0) thr_sm[ty + 16 * i] = bd + MARGIN;
    }
    __syncthreads();

    // ---- phase B: candidate refinement (exact ref-formula), token t by threads (t, t+128) ----
    const int t = tid & 127;
    const int h = tid >> 7;
    const uint32_t* srow = (const uint32_t*)s16 + t * (S_STRIDE16 / 2) + h * 128;
    const float thr = thr_sm[t];
    const float* xrow = latents + (size_t)(t0 + t) * E_DIM + g * DIM;

    // exact xsq (sequential chain, ref order)
    float xsq = 0.0f;
    #pragma unroll 4
    for (int d = 0; d < DIM; ++d) xsq = fmaf(xrow[d], xrow[d], xsq);

    uint64_t best = ~0ull;
    for (int i = 0; i < 128; ++i) {
        __half2 hv = *(const __half2*)(srow + i);
        float2 f = __half22float2(hv);
        #pragma unroll
        for (int sub = 0; sub < 2; ++sub) {
            float sv = (sub == 0) ? f.x : f.y;
            if (sv <= thr) {
                int k = h * 256 + i * 2 + sub;
                const float* wr = W + (size_t)k * DIM;
                float cr = 0.0f;
                #pragma unroll 4
                for (int d = 0; d < DIM; ++d) cr = fmaf(xrow[d], wr[d], cr);
                float tt = xsq + wsq_sm[k];          // fl(x_sq + w_sq)
                float dd = fmaf(-2.0f, cr, tt);      // fl(t - 2*cross): exact ref formula
                uint64_t pk = ((uint64_t)__float_as_uint(dd) << 32) | (uint32_t)k;
                best = (pk < best) ? pk : best;
            }
        }
    }
    if (h == 1) pk_sm[t] = best;
    __syncthreads();
    if (h == 0) {
        uint64_t o = pk_sm[t];
        if (o < best) best = o;
        bk_sm[t] = (int)(best & 0xffffffffu);
    }
    __syncthreads();

    // ---- output + loss ----
    double lsum = 0.0;
    #pragma unroll
    for (int it = 0; it < 16; ++it) {
        int idx = tid + it * THREADS;
        int mm  = idx >> 5;
        int c4  = idx & 31;
        int k   = bk_sm[mm];
        float4 q = *(const float4*)(W + (size_t)k * DIM + c4 * 4);
        float4 x = *(const float4*)(latents + (size_t)(t0 + mm) * E_DIM + g * DIM + c4 * 4);
        float dx = q.x - x.x, dy = q.y - x.y, dz = q.z - x.z, dw = q.w - x.w;
        float4 o;
        o.x = x.x + dx; o.y = x.y + dy; o.z = x.z + dz; o.w = x.w + dw;   // x + (q - x), as ref
        *(float4*)(out + (size_t)(t0 + mm) * E_DIM + g * DIM + c4 * 4) = o;
        lsum += (double)dx * dx + (double)dy * dy + (double)dz * dz + (double)dw * dw;
    }
    #pragma unroll
    for (int off = 16; off; off >>= 1)
        lsum += __shfl_xor_sync(0xffffffffu, lsum, off);
    if (lane == 0) red[wid] = lsum;
    __syncthreads();
    if (tid == 0) {
        double s = 0.0;
        #pragma unroll
        for (int w = 0; w < 8; ++w) s += red[w];
        atomicAdd(&g_loss_acc, s);
    }
}

extern "C" void kernel_launch(void* const* d_in, const int* in_sizes, int n_in,
                              void* d_out, int out_size) {
    const float* latents = (const float*)d_in[0];
    const float* w1 = (const float*)d_in[1];
    const float* w2 = (const float*)d_in[2];
    const float* w3 = (const float*)d_in[3];
    const float* w4 = (const float*)d_in[4];
    float* out = (float*)d_out;

    cudaFuncSetAttribute(vq_main_kernel, cudaFuncAttributeMaxDynamicSharedMemorySize, SMEM_TOTAL);

    vq_init_kernel<<<1, 1>>>();
    vq_prep_kernel<<<(GROUPS * KCODES + 255) / 256, 256>>>(w1, w2, w3, w4);
    dim3 grid(T_TOKENS / MT, GROUPS);
    vq_main_kernel<<<grid, THREADS, SMEM_TOTAL>>>(latents, w1, w2, w3, w4, out);
    vq_finalize_kernel<<<1, 1>>>(out, (long long)out_size - 1);
}

// round 8
// speedup vs baseline: 1.4978x; 1.4978x over previous
#include <cuda_runtime.h>
#include <cstdint>

// ---------------- problem constants ----------------
#define T_TOKENS 32768
#define E_DIM    512
#define GROUPS   4
#define DIM      128
#define KCODES   512

#define MT       128
#define KT       128
#define THREADS  256
#define XS_STRIDE 132
#define WS_STRIDE 132

#define THRTOL   1e-4f   // top-2 gap below which we do exact full rescan (E~1.7e-5, 3x margin)

__device__ float  g_wsq[GROUPS * KCODES];
__device__ double g_loss_acc;

__global__ void vq_init_kernel() { g_loss_acc = 0.0; }

__global__ void vq_finalize_kernel(float* out, long long loss_index) {
    out[loss_index] = (float)(g_loss_acc * (1.25 / 4194304.0));
}

// exact wsq per code row (sequential fp32 chain, same order as round-3 / ref semantics)
__global__ void vq_prep_kernel(const float* __restrict__ w0, const float* __restrict__ w1,
                               const float* __restrict__ w2, const float* __restrict__ w3)
{
    int r = blockIdx.x * blockDim.x + threadIdx.x;
    if (r >= GROUPS * KCODES) return;
    int g = r >> 9, k = r & (KCODES - 1);
    const float* W = (g == 0) ? w0 : (g == 1) ? w1 : (g == 2) ? w2 : w3;
    const float* row = W + (size_t)k * DIM;
    float s = 0.0f;
    #pragma unroll 4
    for (int d = 0; d < DIM; ++d) s = fmaf(row[d], row[d], s);
    g_wsq[r] = s;
}

// packed f32x2 FMA: both lanes round rn, identical to scalar fmaf per lane
#define FMA_F32X2(acc, a, b) \
    asm("fma.rn.f32x2 %0, %1, %2, %0;" : "+l"(acc) : "l"(a), "l"(b))

__device__ __forceinline__ float unpack_sum(unsigned long long v) {
    unsigned int lo, hi;
    asm("mov.b64 {%0, %1}, %2;" : "=r"(lo), "=r"(hi) : "l"(v));
    return __uint_as_float(lo) + __uint_as_float(hi);
}

__global__ __launch_bounds__(THREADS, 1)
void vq_main_kernel(const float* __restrict__ latents,
                    const float* __restrict__ w0, const float* __restrict__ w1,
                    const float* __restrict__ w2, const float* __restrict__ w3,
                    float* __restrict__ out)
{
    extern __shared__ float smem[];
    float* xs     = smem;                        // MT * XS_STRIDE
    float* ws     = xs + MT * XS_STRIDE;         // KT * WS_STRIDE
    float* wsq_sm = ws + KT * WS_STRIDE;         // KCODES
    int*   bk_sm  = (int*)(wsq_sm + KCODES);     // MT
    int*   fl_sm  = bk_sm + MT;                  // MT
    int*   list_sm= fl_sm + MT;                  // MT
    int*   cnt_sm = list_sm + MT;                // 2 (pad to 8B align)
    double* red   = (double*)(cnt_sm + 2);       // 8

    const int g  = blockIdx.y;
    const int t0 = blockIdx.x * MT;
    const float* __restrict__ W = (g == 0) ? w0 : (g == 1) ? w1 : (g == 2) ? w2 : w3;

    const int tid  = threadIdx.x;
    const int wid  = tid >> 5;
    const int lane = tid & 31;
    const int tx   = tid & 15;    // code lane
    const int ty   = tid >> 4;    // token lane

    if (tid == 0) cnt_sm[0] = 0;
    for (int i = tid; i < KCODES; i += THREADS) wsq_sm[i] = g_wsq[g * KCODES + i];

    // ---- load x tile ----
    {
        const int d4 = tid & 31;
        const int mb = tid >> 5;
        #pragma unroll
        for (int r = 0; r < MT / 8; ++r) {
            int m = mb + r * 8;
            float4 v = *(const float4*)(latents + (size_t)(t0 + m) * E_DIM + g * DIM + d4 * 4);
            *(float4*)(xs + m * XS_STRIDE + d4 * 4) = v;
        }
    }

    // top-2 running state per token (8 tokens per thread across 16-lane groups)
    float s1[8], s2[8];
    int   k1[8];
    #pragma unroll
    for (int i = 0; i < 8; ++i) { s1[i] = 3.402823466e38f; s2[i] = 3.402823466e38f; k1[i] = 0; }

    for (int kt = 0; kt < KCODES / KT; ++kt) {
        __syncthreads();
        // ---- load w tile ----
        {
            const int d4 = tid & 31;
            const int kb = tid >> 5;
            #pragma unroll
            for (int r = 0; r < KT / 8; ++r) {
                int k = kb + r * 8;
                float4 v = *(const float4*)(W + (size_t)(kt * KT + k) * DIM + d4 * 4);
                *(float4*)(ws + k * WS_STRIDE + d4 * 4) = v;
            }
        }
        __syncthreads();

        // ---- 8x8 register tile, packed f32x2 accumulation (even/odd d split) ----
        unsigned long long acc2[8][8];
        #pragma unroll
        for (int i = 0; i < 8; ++i)
            #pragma unroll
            for (int j = 0; j < 8; ++j) acc2[i][j] = 0ull;

        for (int d4 = 0; d4 < DIM / 4; ++d4) {
            ulonglong2 xv[8];
            #pragma unroll
            for (int i = 0; i < 8; ++i)
                xv[i] = *(const ulonglong2*)(xs + (ty + 16 * i) * XS_STRIDE + d4 * 4);
            #pragma unroll
            for (int j = 0; j < 8; ++j) {
                ulonglong2 wv = *(const ulonglong2*)(ws + (tx + 16 * j) * WS_STRIDE + d4 * 4);
                #pragma unroll
                for (int i = 0; i < 8; ++i) {
                    FMA_F32X2(acc2[i][j], xv[i].x, wv.x);
                    FMA_F32X2(acc2[i][j], xv[i].y, wv.y);
                }
            }
        }

        // ---- approx s = wsq - 2*cross ; update top-2 ----
        #pragma unroll
        for (int j = 0; j < 8; ++j) {
            int   kk = kt * KT + tx + 16 * j;
            float tw = wsq_sm[kk];
            #pragma unroll
            for (int i = 0; i < 8; ++i) {
                float cr = unpack_sum(acc2[i][j]);
                float s  = fmaf(-2.0f, cr, tw);
                if (s < s1[i]) { s2[i] = s1[i]; s1[i] = s; k1[i] = kk; }
                else if (s < s2[i]) { s2[i] = s; }
            }
        }
    }

    // ---- cross-lane top-2 reduce over 16 code-lanes ----
    #pragma unroll
    for (int i = 0; i < 8; ++i) {
        float a1 = s1[i], a2 = s2[i]; int ak = k1[i];
        #pragma unroll
        for (int off = 1; off < 16; off <<= 1) {
            float o1 = __shfl_xor_sync(0xffffffffu, a1, off);
            int   ok = __shfl_xor_sync(0xffffffffu, ak, off);
            float o2 = __shfl_xor_sync(0xffffffffu, a2, off);
            if (o1 < a1 || (o1 == a1 && ok < ak)) {
                a2 = fminf(a1, o2); a1 = o1; ak = ok;
            } else {
                a2 = fminf(a2, o1);
            }
        }
        if (tx == 0) {
            int t = ty + 16 * i;
            bk_sm[t] = ak;
            fl_sm[t] = (a2 - a1 <= THRTOL) ? 1 : 0;
        }
    }
    __syncthreads();

    // ---- gather tokens needing exact rescan ----
    if (tid < MT && fl_sm[tid]) {
        int pos = atomicAdd(cnt_sm, 1);
        list_sm[pos] = tid;
    }
    __syncthreads();
    const int nfb = cnt_sm[0];

    // ---- fallback: exact full 512-code rescan (bit-exact round-3 formula) ----
    for (int idx = wid; idx < nfb; idx += THREADS / 32) {
        int t = list_sm[idx];
        const float* xrow = xs + t * XS_STRIDE;
        float xsq = 0.0f;
        #pragma unroll 4
        for (int d = 0; d < DIM; ++d) xsq = fmaf(xrow[d], xrow[d], xsq);
        uint64_t best = ~0ull;
        for (int u = 0; u < KCODES / 32; ++u) {
            int k = lane + 32 * u;
            const float* wr = W + (size_t)k * DIM;
            float cr = 0.0f;
            #pragma unroll 4
            for (int d = 0; d < DIM; ++d) cr = fmaf(xrow[d], wr[d], cr);
            float tt = xsq + wsq_sm[k];        // fl(x_sq + w_sq)
            float dd = fmaf(-2.0f, cr, tt);    // fl(t - 2*cross): exact ref formula
            uint64_t pk = ((uint64_t)__float_as_uint(dd) << 32) | (uint32_t)k;
            best = (pk < best) ? pk : best;
        }
        #pragma unroll
        for (int off = 16; off; off >>= 1) {
            uint64_t o = __shfl_xor_sync(0xffffffffu, best, off);
            best = (o < best) ? o : best;
        }
        if (lane == 0) bk_sm[t] = (int)(best & 0xffffffffu);
    }
    __syncthreads();

    // ---- output + loss (round-3 epilogue, proven bit-exact) ----
    double lsum = 0.0;
    #pragma unroll
    for (int r = 0; r < (MT * 32) / THREADS; ++r) {
        int idx = tid + r * THREADS;
        int m   = idx >> 5;
        int c4  = idx & 31;
        int bk  = bk_sm[m];
        float4 q = *(const float4*)(W + (size_t)bk * DIM + c4 * 4);
        float4 x = *(const float4*)(xs + m * XS_STRIDE + c4 * 4);
        float dx = q.x - x.x, dy = q.y - x.y, dz = q.z - x.z, dw = q.w - x.w;
        float4 o;
        o.x = x.x + dx; o.y = x.y + dy; o.z = x.z + dz; o.w = x.w + dw;   // x + (q - x), as ref
        *(float4*)(out + (size_t)(t0 + m) * E_DIM + g * DIM + c4 * 4) = o;
        lsum += (double)dx * dx + (double)dy * dy + (double)dz * dz + (double)dw * dw;
    }
    #pragma unroll
    for (int off = 16; off; off >>= 1)
        lsum += __shfl_xor_sync(0xffffffffu, lsum, off);
    if (lane == 0) red[wid] = lsum;
    __syncthreads();
    if (tid == 0) {
        double s = 0.0;
        #pragma unroll
        for (int w = 0; w < THREADS / 32; ++w) s += red[w];
        atomicAdd(&g_loss_acc, s);
    }
}

extern "C" void kernel_launch(void* const* d_in, const int* in_sizes, int n_in,
                              void* d_out, int out_size) {
    const float* latents = (const float*)d_in[0];
    const float* w1 = (const float*)d_in[1];
    const float* w2 = (const float*)d_in[2];
    const float* w3 = (const float*)d_in[3];
    const float* w4 = (const float*)d_in[4];
    float* out = (float*)d_out;

    size_t smem_bytes = (size_t)(MT * XS_STRIDE + KT * WS_STRIDE + KCODES) * sizeof(float)
                      + (size_t)(3 * MT + 2) * sizeof(int) + 8 * sizeof(double);
    cudaFuncSetAttribute(vq_main_kernel, cudaFuncAttributeMaxDynamicSharedMemorySize,
                         (int)smem_bytes);

    vq_init_kernel<<<1, 1>>>();
    vq_prep_kernel<<<(GROUPS * KCODES + 255) / 256, 256>>>(w1, w2, w3, w4);
    dim3 grid(T_TOKENS / MT, GROUPS);
    vq_main_kernel<<<grid, THREADS, smem_bytes>>>(latents, w1, w2, w3, w4, out);
    vq_finalize_kernel<<<1, 1>>>(out, (long long)out_size - 1);
}